// round 14
// baseline (speedup 1.0000x reference)
#include <cuda_runtime.h>
#include <cuda_fp16.h>

#define BN     32
#define HH     1024
#define WW     1024
#define NPIX   (HH * WW)
#define TOTAL  ((size_t)BN * NPIX)
#define ITERS  10
#define RY     16
#define STRIPS (HH / RY)            // 64 blocks per batch
#define GRID   (BN * STRIPS)       // 2048 blocks, single wave

// ---- static scratch; ALL zero-initialized (required by reset protocol) ----
__device__ __half   g_bufA[TOTAL];
__device__ __half   g_bufB[TOTAL];
__device__ unsigned g_maxb[ITERS][BN];      // max bits (floats >= 0)
__device__ unsigned g_minv[ITERS][BN];      // ~min bits (zero-init = identity)
__device__ double   g_sum [ITERS][BN];
__device__ unsigned g_cnt [ITERS][BN];      // barrier counters (1..9 used)
__device__ double   g_loss;
__device__ unsigned g_done;

__device__ __forceinline__ float bnd(float p, int t) {
    float v = p - (t == 0 ? 1.0f : 0.0f);
    return v * v;
}
__device__ __forceinline__ __half2 U2H(unsigned u) {
    return *reinterpret_cast<__half2*>(&u);
}
__device__ __forceinline__ unsigned H2U(__half2 h) {
    return *reinterpret_cast<unsigned*>(&h);
}

// ---------------------------------------------------------------------------
// block reduction (128 threads) -> atomics into stats[k][b]
// min stored inverted (atomicMax of ~bits) so zero-init is the identity.
// ---------------------------------------------------------------------------
__device__ __forceinline__ void reduce_stats(float vmax, float vmin, float vsum,
                                             int b, int k)
{
    const int lane = threadIdx.x & 31;
    const int warp = threadIdx.x >> 5;
    #pragma unroll
    for (int d = 16; d > 0; d >>= 1) {
        vmax  = fmaxf(vmax, __shfl_xor_sync(0xffffffffu, vmax, d));
        vmin  = fminf(vmin, __shfl_xor_sync(0xffffffffu, vmin, d));
        vsum +=             __shfl_xor_sync(0xffffffffu, vsum, d);
    }
    __shared__ float smax[4], smin[4], ssum[4];
    if (lane == 0) { smax[warp] = vmax; smin[warp] = vmin; ssum[warp] = vsum; }
    __syncthreads();
    if (warp == 0) {
        vmax = (lane < 4) ? smax[lane] : 0.0f;
        vmin = (lane < 4) ? smin[lane] : __int_as_float(0x7f800000);
        vsum = (lane < 4) ? ssum[lane] : 0.0f;
        #pragma unroll
        for (int d = 2; d > 0; d >>= 1) {
            vmax  = fmaxf(vmax, __shfl_xor_sync(0xffffffffu, vmax, d));
            vmin  = fminf(vmin, __shfl_xor_sync(0xffffffffu, vmin, d));
            vsum +=             __shfl_xor_sync(0xffffffffu, vsum, d);
        }
        if (lane == 0) {
            atomicMax(&g_maxb[k][b], __float_as_uint(vmax));
            atomicMax(&g_minv[k][b], ~__float_as_uint(vmin));
            atomicAdd(&g_sum[k][b], (double)vsum);
        }
    }
}

// ---------------------------------------------------------------------------
// Pass 0 kernel (R11 fp32 body verbatim): fused bound + erosion0 -> g_bufA,
// stats[0]. Own launch => own register allocation + L1 flush into pass 1.
// grid = (STRIPS, BN), block = 128.
// ---------------------------------------------------------------------------
__global__ void __launch_bounds__(128) pass0_kernel(
    const float* __restrict__ pred, const int* __restrict__ tgt)
{
    const int b    = blockIdx.y;
    const int y0   = blockIdx.x * RY;
    const int t    = threadIdx.x;
    const int lane = t & 31;
    const int x0   = t << 3;
    const size_t bb = (size_t)b * NPIX;

    float rv[3][8];
    float rhl[3], rhr[3];

    auto loadrow = [&](int slot, int y) {
        if ((unsigned)y < (unsigned)HH) {
            const float* pr  = pred + bb + (size_t)y * WW;
            const int*   trw = tgt  + bb + (size_t)y * WW;
            float4 p0 = *(const float4*)(pr + x0);
            float4 p1 = *(const float4*)(pr + x0 + 4);
            int4   q0 = *(const int4*)(trw + x0);
            int4   q1 = *(const int4*)(trw + x0 + 4);
            rv[slot][0] = bnd(p0.x, q0.x); rv[slot][1] = bnd(p0.y, q0.y);
            rv[slot][2] = bnd(p0.z, q0.z); rv[slot][3] = bnd(p0.w, q0.w);
            rv[slot][4] = bnd(p1.x, q1.x); rv[slot][5] = bnd(p1.y, q1.y);
            rv[slot][6] = bnd(p1.z, q1.z); rv[slot][7] = bnd(p1.w, q1.w);
            float l = __shfl_up_sync(0xffffffffu, rv[slot][7], 1);
            if (lane == 0)  l = (x0 > 0)      ? bnd(pr[x0 - 1], trw[x0 - 1]) : 0.0f;
            float r = __shfl_down_sync(0xffffffffu, rv[slot][0], 1);
            if (lane == 31) r = (x0 + 8 < WW) ? bnd(pr[x0 + 8], trw[x0 + 8]) : 0.0f;
            rhl[slot] = l; rhr[slot] = r;
        } else {
            #pragma unroll
            for (int j = 0; j < 8; ++j) rv[slot][j] = 0.0f;
            rhl[slot] = rhr[slot] = 0.0f;
        }
    };

    loadrow(0, y0 - 1);
    loadrow(1, y0);

    float vsum = 0.0f;
    __half2 hmax2 = __float2half2_rn(0.0f);
    __half2 hmin2 = __float2half2_rn(65504.0f);

    #pragma unroll
    for (int i = 0; i < RY; ++i) {
        const int y = y0 + i;
        const int pslot = i % 3, cslot = (i + 1) % 3, nslot = (i + 2) % 3;
        loadrow(nslot, y + 1);

        const float* P  = rv[pslot];
        const float* C  = rv[cslot];
        const float* Nr = rv[nslot];

        float e[8];
        #pragma unroll
        for (int j = 0; j < 8; ++j) {
            float lf = (j == 0) ? rhl[cslot] : C[j - 1];
            float rf = (j == 7) ? rhr[cslot] : C[j + 1];
            e[j] = fmaxf(fmaf(0.2f, (C[j] + P[j]) + (Nr[j] + lf) + rf, -0.5f), 0.0f);
        }

        union { uint4 u4; __half2 h2[4]; } pk;
        #pragma unroll
        for (int j = 0; j < 4; ++j)
            pk.h2[j] = __floats2half2_rn(e[2 * j], e[2 * j + 1]);
        *reinterpret_cast<uint4*>(g_bufA + bb + (size_t)y * WW + x0) = pk.u4;

        #pragma unroll
        for (int j = 0; j < 4; ++j) {
            hmax2 = __hmax2(hmax2, pk.h2[j]);
            hmin2 = __hmin2(hmin2, pk.h2[j]);
        }
        vsum += ((e[0] + e[1]) + (e[2] + e[3])) + ((e[4] + e[5]) + (e[6] + e[7]));
    }

    float vmax = fmaxf(__low2float(hmax2), __high2float(hmax2));
    float vmin = fminf(__low2float(hmin2), __high2float(hmin2));
    reduce_stats(vmax, vmin, vsum, b, 0);
}

// ---------------------------------------------------------------------------
// Per-batch software barrier (64 arrivals). ALL threads fence first (publish
// their own STGs gpu-wide); post-spin fence emits CCTL.IVALL -> L1D
// invalidate, replacing the per-launch flush. Last arriver at barrier k
// resets cnt[k-1] (k>=2; all 64 provably past it).
// ---------------------------------------------------------------------------
__device__ __forceinline__ void batch_barrier(int k, int b)
{
    __threadfence();
    __syncthreads();
    if (threadIdx.x == 0) {
        unsigned r = atomicAdd(&g_cnt[k][b], 1u);
        if (r == (unsigned)(STRIPS - 1) && k > 1)
            atomicExch(&g_cnt[k - 1][b], 0u);
        volatile unsigned* p = &g_cnt[k][b];
        while (*p < (unsigned)STRIPS) __nanosleep(64);
        __threadfence();
    }
    __syncthreads();
}

// ---------------------------------------------------------------------------
// Stencil pass body (identical arithmetic to R11 stencil_kernel).
// ---------------------------------------------------------------------------
__device__ __forceinline__ void run_stencil(const __half* __restrict__ in,
                                            __half* __restrict__ out,
                                            int b, int y0, int k,
                                            float sf, float of)
{
    const int t = threadIdx.x, lane = t & 31;
    const int x0 = t << 3;
    const size_t bb = (size_t)b * NPIX;
    const __half2 s2 = __float2half2_rn(sf);
    const __half2 o2 = __float2half2_rn(of);
    const __half  sh = __low2half(s2);
    const __half  oh = __low2half(o2);
    const __half2 c02   = __float2half2_rn(0.2f);
    const __half2 cm05  = __float2half2_rn(-0.5f);
    const __half2 zero2 = __float2half2_rn(0.0f);

    unsigned rw[3][4];
    unsigned eL[3], eR[3];

    auto loadrow = [&](int slot, int y) {
        if ((unsigned)y < (unsigned)HH) {
            const __half* rp = in + bb + (size_t)y * WW;
            uint4 raw = *reinterpret_cast<const uint4*>(rp + x0);
            rw[slot][0] = H2U(__hfma2(U2H(raw.x), s2, o2));
            rw[slot][1] = H2U(__hfma2(U2H(raw.y), s2, o2));
            rw[slot][2] = H2U(__hfma2(U2H(raw.z), s2, o2));
            rw[slot][3] = H2U(__hfma2(U2H(raw.w), s2, o2));
            unsigned L = __shfl_up_sync(0xffffffffu, rw[slot][3], 1);
            unsigned R = __shfl_down_sync(0xffffffffu, rw[slot][0], 1);
            if (lane == 0)
                L = (x0 > 0)
                  ? ((unsigned)__half_as_ushort(__hfma(rp[x0 - 1], sh, oh)) << 16)
                  : 0u;
            if (lane == 31)
                R = (x0 + 8 < WW)
                  ? (unsigned)__half_as_ushort(__hfma(rp[x0 + 8], sh, oh))
                  : 0u;
            eL[slot] = L; eR[slot] = R;
        } else {
            rw[slot][0] = rw[slot][1] = rw[slot][2] = rw[slot][3] = 0u;
            eL[slot] = eR[slot] = 0u;
        }
    };

    loadrow(0, y0 - 1);
    loadrow(1, y0);

    float vsum = 0.0f;
    __half2 hmax2 = zero2;
    __half2 hmin2 = __float2half2_rn(65504.0f);

    #pragma unroll
    for (int i = 0; i < RY; ++i) {
        const int y = y0 + i;
        const int pslot = i % 3, cslot = (i + 1) % 3, nslot = (i + 2) % 3;
        loadrow(nslot, y + 1);

        const unsigned* C  = rw[cslot];
        const unsigned* P  = rw[pslot];
        const unsigned* Nx = rw[nslot];
        unsigned E0 = eL[cslot], E5 = eR[cslot];
        unsigned tt[5];
        tt[0] = __byte_perm(E0,   C[0], 0x5432);
        tt[1] = __byte_perm(C[0], C[1], 0x5432);
        tt[2] = __byte_perm(C[1], C[2], 0x5432);
        tt[3] = __byte_perm(C[2], C[3], 0x5432);
        tt[4] = __byte_perm(C[3], E5,   0x5432);

        __half2 e[4];
        #pragma unroll
        for (int j = 0; j < 4; ++j) {
            __half2 vert  = __hadd2(__hadd2(U2H(C[j]), U2H(P[j])), U2H(Nx[j]));
            __half2 horiz = __hadd2(U2H(tt[j]), U2H(tt[j + 1]));
            e[j] = __hmax2(__hfma2(__hadd2(vert, horiz), c02, cm05), zero2);
        }

        uint4 pk;
        pk.x = H2U(e[0]); pk.y = H2U(e[1]); pk.z = H2U(e[2]); pk.w = H2U(e[3]);
        *reinterpret_cast<uint4*>(out + bb + (size_t)y * WW + x0) = pk;

        hmax2 = __hmax2(hmax2, __hmax2(__hmax2(e[0], e[1]), __hmax2(e[2], e[3])));
        hmin2 = __hmin2(hmin2, __hmin2(__hmin2(e[0], e[1]), __hmin2(e[2], e[3])));
        __half2 sr = __hadd2(__hadd2(e[0], e[1]), __hadd2(e[2], e[3]));
        float2 f = __half22float2(sr);
        vsum += f.x + f.y;
    }

    float vmax = fmaxf(__low2float(hmax2), __high2float(hmax2));
    float vmin = fminf(__low2float(hmin2), __high2float(hmin2));
    reduce_stats(vmax, vmin, vsum, b, k);
}

// ---------------------------------------------------------------------------
// Persistent kernel: passes 1..9 + per-batch loss, per-batch barriers.
// grid = 2048 (one wave @ 14 blocks/SM guaranteed by launch_bounds).
// ---------------------------------------------------------------------------
__global__ void __launch_bounds__(128, 14) persist_kernel(float* __restrict__ out)
{
    const int bid = blockIdx.x;
    const int b   = bid >> 6;            // batch (32)
    const int y0  = (bid & 63) * RY;     // strip
    const int t   = threadIdx.x;

    #pragma unroll 1
    for (int k = 1; k < ITERS; ++k) {
        const float emax = __uint_as_float(g_maxb[k - 1][b]);
        const float emin = __uint_as_float(~g_minv[k - 1][b]);
        const float den  = emax - emin;
        const float sf = (den != 0.0f) ? 1.0f / den  : 1.0f;
        const float of = (den != 0.0f) ? -emin / den : 0.0f;
        if (k & 1) run_stencil(g_bufA, g_bufB, b, y0, k, sf, of);
        else       run_stencil(g_bufB, g_bufA, b, y0, k, sf, of);
        if (k < ITERS - 1) batch_barrier(k, b);
    }

    // final arrival (counter ITERS-1 = 9); only strip 0 spins on it.
    __threadfence();
    __syncthreads();
    if (t == 0) {
        unsigned r = atomicAdd(&g_cnt[ITERS - 1][b], 1u);
        if (r == (unsigned)(STRIPS - 1))
            atomicExch(&g_cnt[ITERS - 2][b], 0u);
    }

    if (y0 == 0 && t == 0) {
        volatile unsigned* p = &g_cnt[ITERS - 1][b];
        while (*p < (unsigned)STRIPS) __nanosleep(128);
        __threadfence();

        double loss = 0.0;
        #pragma unroll
        for (int k = 0; k < ITERS; ++k) {
            float emax = __uint_as_float(g_maxb[k][b]);
            float emin = __uint_as_float(~g_minv[k][b]);
            double S   = g_sum[k][b];
            float den  = emax - emin;
            double contrib = (den != 0.0f)
                ? (S - (double)NPIX * (double)emin) / (double)den
                : S;
            loss += contrib * (double)((k + 1) * (k + 1));
            // reset stats for next graph replay
            g_maxb[k][b] = 0u;
            g_minv[k][b] = 0u;
            g_sum [k][b] = 0.0;
        }
        atomicExch(&g_cnt[ITERS - 1][b], 0u);

        atomicAdd(&g_loss, loss);
        __threadfence();
        unsigned d = atomicAdd(&g_done, 1u);
        if (d == (unsigned)(BN - 1)) {
            double total = atomicAdd(&g_loss, 0.0);
            out[0] = (float)(total / ((double)BN * (double)NPIX));
            atomicExch((unsigned long long*)&g_loss, 0ull);
            atomicExch(&g_done, 0u);
        }
    }
}

// ---------------------------------------------------------------------------
extern "C" void kernel_launch(void* const* d_in, const int* in_sizes, int n_in,
                              void* d_out, int out_size)
{
    const float* pred   = (const float*)d_in[0];
    const int*   target = (const int*)d_in[1];
    float*       out    = (float*)d_out;

    dim3 grid(STRIPS, BN);
    pass0_kernel<<<grid, 128>>>(pred, target);
    persist_kernel<<<GRID, 128>>>(out);
}

// round 15
// speedup vs baseline: 1.3431x; 1.3431x over previous
#include <cuda_runtime.h>
#include <cuda_fp16.h>

#define BN    32
#define HH    1024
#define WW    1024
#define NPIX  (HH * WW)
#define TOTAL ((size_t)BN * NPIX)
#define ITERS 10
#define RY    8

// ---- static scratch; ALL zero-initialized (self-reset protocol) ----
__device__ __half   g_bufA[TOTAL];          // 64 MB
__device__ __half   g_bufB[TOTAL];          // 64 MB
__device__ unsigned g_maxb[ITERS][BN];      // max bits (floats >= 0)
__device__ unsigned g_minv[ITERS][BN];      // ~min bits (zero-init = identity)
__device__ double   g_sum [ITERS][BN];

__device__ __forceinline__ float bnd(float p, int t) {
    float v = p - (t == 0 ? 1.0f : 0.0f);
    return v * v;
}
__device__ __forceinline__ __half2 U2H(unsigned u) {
    return *reinterpret_cast<__half2*>(&u);
}
__device__ __forceinline__ unsigned H2U(__half2 h) {
    return *reinterpret_cast<unsigned*>(&h);
}

// ---------------------------------------------------------------------------
// block reduction (128 threads) -> atomics into stats[k][b]
// min stored inverted (atomicMax of ~bits) so zero-init is the identity.
// ---------------------------------------------------------------------------
__device__ __forceinline__ void reduce_stats(float vmax, float vmin, float vsum,
                                             int b, int k)
{
    const int lane = threadIdx.x & 31;
    const int warp = threadIdx.x >> 5;
    #pragma unroll
    for (int d = 16; d > 0; d >>= 1) {
        vmax  = fmaxf(vmax, __shfl_xor_sync(0xffffffffu, vmax, d));
        vmin  = fminf(vmin, __shfl_xor_sync(0xffffffffu, vmin, d));
        vsum +=             __shfl_xor_sync(0xffffffffu, vsum, d);
    }
    __shared__ float smax[4], smin[4], ssum[4];
    if (lane == 0) { smax[warp] = vmax; smin[warp] = vmin; ssum[warp] = vsum; }
    __syncthreads();
    if (warp == 0) {
        vmax = (lane < 4) ? smax[lane] : 0.0f;
        vmin = (lane < 4) ? smin[lane] : __int_as_float(0x7f800000);
        vsum = (lane < 4) ? ssum[lane] : 0.0f;
        #pragma unroll
        for (int d = 2; d > 0; d >>= 1) {
            vmax  = fmaxf(vmax, __shfl_xor_sync(0xffffffffu, vmax, d));
            vmin  = fminf(vmin, __shfl_xor_sync(0xffffffffu, vmin, d));
            vsum +=             __shfl_xor_sync(0xffffffffu, vsum, d);
        }
        if (lane == 0) {
            atomicMax(&g_maxb[k][b], __float_as_uint(vmax));
            atomicMax(&g_minv[k][b], ~__float_as_uint(vmin));
            atomicAdd(&g_sum[k][b], (double)vsum);
        }
    }
}

// ---------------------------------------------------------------------------
// Stencil passes 1..9 in packed half2 arithmetic (normalize-on-load) with
// vertical register rolling over an RY-row strip (3 slots, zero prefetch
// distance — TLP does the latency hiding; plain loads keep L1 hits).
// DIR==0: A->B, DIR==1: B->A. grid = (HH/RY, BN), block = 128, 8 px/thread.
// ---------------------------------------------------------------------------
template <int DIR>
__global__ void __launch_bounds__(128) stencil_kernel(int k)
{
    const __half* __restrict__ in  = DIR ? g_bufB : g_bufA;
    __half*       __restrict__ out = DIR ? g_bufA : g_bufB;

    const int b    = blockIdx.y;
    const int y0   = blockIdx.x * RY;
    const int t    = threadIdx.x;
    const int lane = t & 31;
    const int x0   = t << 3;
    const size_t bb = (size_t)b * NPIX;

    const float emax = __uint_as_float(g_maxb[k - 1][b]);
    const float emin = __uint_as_float(~g_minv[k - 1][b]);
    const float den  = emax - emin;
    const float sf = (den != 0.0f) ? 1.0f / den  : 1.0f;
    const float of = (den != 0.0f) ? -emin / den : 0.0f;
    const __half2 s2 = __float2half2_rn(sf);
    const __half2 o2 = __float2half2_rn(of);
    const __half  sh = __low2half(s2);
    const __half  oh = __low2half(o2);
    const __half2 c02   = __float2half2_rn(0.2f);
    const __half2 cm05  = __float2half2_rn(-0.5f);
    const __half2 zero2 = __float2half2_rn(0.0f);

    unsigned rw[3][4];            // normalized rows (half2 as uint)
    unsigned eL[3], eR[3];        // halo regs: .hi of eL, .lo of eR valid

    auto loadrow = [&](int slot, int y) {
        if ((unsigned)y < (unsigned)HH) {   // uniform per block
            const __half* rp = in + bb + (size_t)y * WW;
            uint4 raw = *reinterpret_cast<const uint4*>(rp + x0);
            rw[slot][0] = H2U(__hfma2(U2H(raw.x), s2, o2));
            rw[slot][1] = H2U(__hfma2(U2H(raw.y), s2, o2));
            rw[slot][2] = H2U(__hfma2(U2H(raw.z), s2, o2));
            rw[slot][3] = H2U(__hfma2(U2H(raw.w), s2, o2));
            unsigned L = __shfl_up_sync(0xffffffffu, rw[slot][3], 1);
            unsigned R = __shfl_down_sync(0xffffffffu, rw[slot][0], 1);
            if (lane == 0)
                L = (x0 > 0)
                  ? ((unsigned)__half_as_ushort(__hfma(rp[x0 - 1], sh, oh)) << 16)
                  : 0u;
            if (lane == 31)
                R = (x0 + 8 < WW)
                  ? (unsigned)__half_as_ushort(__hfma(rp[x0 + 8], sh, oh))
                  : 0u;
            eL[slot] = L; eR[slot] = R;
        } else {
            rw[slot][0] = rw[slot][1] = rw[slot][2] = rw[slot][3] = 0u;
            eL[slot] = eR[slot] = 0u;
        }
    };

    loadrow(0, y0 - 1);
    loadrow(1, y0);

    float vsum = 0.0f;
    __half2 hmax2 = zero2;
    __half2 hmin2 = __float2half2_rn(65504.0f);

    #pragma unroll
    for (int i = 0; i < RY; ++i) {
        const int y = y0 + i;
        const int pslot = i % 3, cslot = (i + 1) % 3, nslot = (i + 2) % 3;
        loadrow(nslot, y + 1);

        const unsigned* C  = rw[cslot];
        const unsigned* P  = rw[pslot];
        const unsigned* Nx = rw[nslot];

        unsigned E0 = eL[cslot], E5 = eR[cslot];
        unsigned tt[5];
        tt[0] = __byte_perm(E0,   C[0], 0x5432);
        tt[1] = __byte_perm(C[0], C[1], 0x5432);
        tt[2] = __byte_perm(C[1], C[2], 0x5432);
        tt[3] = __byte_perm(C[2], C[3], 0x5432);
        tt[4] = __byte_perm(C[3], E5,   0x5432);

        __half2 e[4];
        #pragma unroll
        for (int j = 0; j < 4; ++j) {
            __half2 vert  = __hadd2(__hadd2(U2H(C[j]), U2H(P[j])), U2H(Nx[j]));
            __half2 horiz = __hadd2(U2H(tt[j]), U2H(tt[j + 1]));
            __half2 sm    = __hadd2(vert, horiz);
            e[j] = __hmax2(__hfma2(sm, c02, cm05), zero2);
        }

        uint4 pk;
        pk.x = H2U(e[0]); pk.y = H2U(e[1]); pk.z = H2U(e[2]); pk.w = H2U(e[3]);
        *reinterpret_cast<uint4*>(out + bb + (size_t)y * WW + x0) = pk;

        hmax2 = __hmax2(hmax2, __hmax2(__hmax2(e[0], e[1]), __hmax2(e[2], e[3])));
        hmin2 = __hmin2(hmin2, __hmin2(__hmin2(e[0], e[1]), __hmin2(e[2], e[3])));
        __half2 sr = __hadd2(__hadd2(e[0], e[1]), __hadd2(e[2], e[3]));
        float2 f = __half22float2(sr);
        vsum += f.x + f.y;
    }

    float vmax = fmaxf(__low2float(hmax2), __high2float(hmax2));
    float vmin = fminf(__low2float(hmin2), __high2float(hmin2));
    reduce_stats(vmax, vmin, vsum, b, k);
}

// ---------------------------------------------------------------------------
// Pass 0 (fused bound + erosion0), fp32 compute (input-bandwidth-bound).
// grid = (HH/RY, BN).
// ---------------------------------------------------------------------------
__global__ void __launch_bounds__(128) pass0_kernel(
    const float* __restrict__ pred, const int* __restrict__ tgt)
{
    const int b    = blockIdx.y;
    const int y0   = blockIdx.x * RY;
    const int t    = threadIdx.x;
    const int lane = t & 31;
    const int x0   = t << 3;
    const size_t bb = (size_t)b * NPIX;

    float rv[3][8];
    float rhl[3], rhr[3];

    auto loadrow = [&](int slot, int y) {
        if ((unsigned)y < (unsigned)HH) {
            const float* pr  = pred + bb + (size_t)y * WW;
            const int*   trw = tgt  + bb + (size_t)y * WW;
            float4 p0 = *(const float4*)(pr + x0);
            float4 p1 = *(const float4*)(pr + x0 + 4);
            int4   q0 = *(const int4*)(trw + x0);
            int4   q1 = *(const int4*)(trw + x0 + 4);
            rv[slot][0] = bnd(p0.x, q0.x); rv[slot][1] = bnd(p0.y, q0.y);
            rv[slot][2] = bnd(p0.z, q0.z); rv[slot][3] = bnd(p0.w, q0.w);
            rv[slot][4] = bnd(p1.x, q1.x); rv[slot][5] = bnd(p1.y, q1.y);
            rv[slot][6] = bnd(p1.z, q1.z); rv[slot][7] = bnd(p1.w, q1.w);
            float l = __shfl_up_sync(0xffffffffu, rv[slot][7], 1);
            if (lane == 0)  l = (x0 > 0)      ? bnd(pr[x0 - 1], trw[x0 - 1]) : 0.0f;
            float r = __shfl_down_sync(0xffffffffu, rv[slot][0], 1);
            if (lane == 31) r = (x0 + 8 < WW) ? bnd(pr[x0 + 8], trw[x0 + 8]) : 0.0f;
            rhl[slot] = l; rhr[slot] = r;
        } else {
            #pragma unroll
            for (int j = 0; j < 8; ++j) rv[slot][j] = 0.0f;
            rhl[slot] = rhr[slot] = 0.0f;
        }
    };

    loadrow(0, y0 - 1);
    loadrow(1, y0);

    float vsum = 0.0f;
    __half2 hmax2 = __float2half2_rn(0.0f);
    __half2 hmin2 = __float2half2_rn(65504.0f);

    #pragma unroll
    for (int i = 0; i < RY; ++i) {
        const int y = y0 + i;
        const int pslot = i % 3, cslot = (i + 1) % 3, nslot = (i + 2) % 3;
        loadrow(nslot, y + 1);

        const float* P  = rv[pslot];
        const float* C  = rv[cslot];
        const float* Nr = rv[nslot];

        float e[8];
        #pragma unroll
        for (int j = 0; j < 8; ++j) {
            float lf = (j == 0) ? rhl[cslot] : C[j - 1];
            float rf = (j == 7) ? rhr[cslot] : C[j + 1];
            e[j] = fmaxf(fmaf(0.2f, (C[j] + P[j]) + (Nr[j] + lf) + rf, -0.5f), 0.0f);
        }

        union { uint4 u4; __half2 h2[4]; } pk;
        #pragma unroll
        for (int j = 0; j < 4; ++j)
            pk.h2[j] = __floats2half2_rn(e[2 * j], e[2 * j + 1]);
        *reinterpret_cast<uint4*>(g_bufA + bb + (size_t)y * WW + x0) = pk.u4;

        #pragma unroll
        for (int j = 0; j < 4; ++j) {
            hmax2 = __hmax2(hmax2, pk.h2[j]);
            hmin2 = __hmin2(hmin2, pk.h2[j]);
        }
        vsum += ((e[0] + e[1]) + (e[2] + e[3])) + ((e[4] + e[5]) + (e[6] + e[7]));
    }

    float vmax = fmaxf(__low2float(hmax2), __high2float(hmax2));
    float vmin = fminf(__low2float(hmin2), __high2float(hmin2));
    reduce_stats(vmax, vmin, vsum, b, 0);
}

// ---------------------------------------------------------------------------
// Final: analytic loss from the 10 stat triples, then SELF-RESET all stats
// to zero (runs after all stencil passes by stream order; restores the
// zero-initialized state so the captured graph replays deterministically).
// ---------------------------------------------------------------------------
__global__ void finish_kernel(float* __restrict__ out)
{
    const int b = threadIdx.x;    // 0..31
    double loss = 0.0;
    #pragma unroll
    for (int k = 0; k < ITERS; ++k) {
        float emax = __uint_as_float(g_maxb[k][b]);
        float emin = __uint_as_float(~g_minv[k][b]);
        double S   = g_sum[k][b];
        float den  = emax - emin;
        double contrib = (den != 0.0f)
            ? (S - (double)NPIX * (double)emin) / (double)den
            : S;
        loss += contrib * (double)((k + 1) * (k + 1));
        g_maxb[k][b] = 0u;
        g_minv[k][b] = 0u;
        g_sum [k][b] = 0.0;
    }
    #pragma unroll
    for (int d = 16; d > 0; d >>= 1)
        loss += __shfl_xor_sync(0xffffffffu, loss, d);
    if (b == 0)
        out[0] = (float)(loss / ((double)BN * (double)NPIX));
}

// ---------------------------------------------------------------------------
extern "C" void kernel_launch(void* const* d_in, const int* in_sizes, int n_in,
                              void* d_out, int out_size)
{
    const float* pred   = (const float*)d_in[0];
    const int*   target = (const int*)d_in[1];
    float*       out    = (float*)d_out;

    dim3 grid(HH / RY, BN);
    pass0_kernel<<<grid, 128>>>(pred, target);

    for (int k = 1; k < ITERS; ++k) {
        if (k & 1) stencil_kernel<0><<<grid, 128>>>(k);   // A -> B
        else       stencil_kernel<1><<<grid, 128>>>(k);   // B -> A
    }

    finish_kernel<<<1, 32>>>(out);
}